// round 2
// baseline (speedup 1.0000x reference)
#include <cuda_runtime.h>
#include <math.h>

#define TT    1024            // timesteps
#define BATCH 1024            // batch
#define HDIM  100             // hidden
#define GDIM  400             // 4*H gates
#define WPAD  104             // padded W row (float4-aligned, conflict-free)
#define BPB   8               // batch elements per block (recurrent kernels)
#define NB1   (BATCH / BPB)   // 128 blocks
#define NT1   512             // threads per recurrent block

// ---- scratch (static device globals; allocation-free) ----
__device__ float g_h1[(size_t)TT * BATCH * HDIM];    // 400 MB: layer-0 hidden states
__device__ float g_pre1[(size_t)TT * BATCH * GDIM];  // 1.6 GB: layer-1 gate pre-activations

__device__ __forceinline__ float sigmf(float x) { return 1.0f / (1.0f + __expf(-x)); }

// ============================================================================
// Phase 1: layer-0 LSTM recurrence. Each block owns BPB batch elems for all T.
// smem: W_hh0 (padded), combined bias, W_ih0, gate buffer, h, c, x-stage.
// ============================================================================
__global__ void __launch_bounds__(NT1, 1) lstm_layer0_kernel(
    const float* __restrict__ x,      // [1024][3][1024]
    const float* __restrict__ Wih,    // [400][3]
    const float* __restrict__ Whh,    // [400][100]
    const float* __restrict__ bih,
    const float* __restrict__ bhh)
{
    extern __shared__ float sm[];
    float* sW    = sm;                       // 400*104
    float* sBias = sW + GDIM * WPAD;         // 400
    float* sWin  = sBias + GDIM;             // 1200
    float* sGate = sWin + GDIM * 3;          // 8*400
    float* sH    = sGate + BPB * GDIM;       // 8*100
    float* sC    = sH + BPB * HDIM;          // 8*100
    float* sX    = sC + BPB * HDIM;          // 8*3

    const int tid = threadIdx.x;
    const int bg0 = blockIdx.x * BPB;

    for (int lin = tid; lin < GDIM * HDIM; lin += NT1)
        sW[(lin / HDIM) * WPAD + (lin % HDIM)] = Whh[lin];
    for (int lin = tid; lin < GDIM; lin += NT1) sBias[lin] = bih[lin] + bhh[lin];
    for (int lin = tid; lin < GDIM * 3; lin += NT1) sWin[lin] = Wih[lin];
    for (int lin = tid; lin < BPB * HDIM; lin += NT1) { sH[lin] = 0.0f; sC[lin] = 0.0f; }
    __syncthreads();

    for (int t = 0; t < TT; t++) {
        if (tid < BPB * 3) {
            int b = tid / 3, c = tid % 3;
            sX[tid] = x[((size_t)(bg0 + b) * 3 + c) * 1024 + t];
        }
        __syncthreads();

        // gate pre-activations + recurrent matvec
        for (int idx = tid; idx < BPB * GDIM; idx += NT1) {
            int b = idx & (BPB - 1);
            int j = idx >> 3;
            float acc0 = sBias[j]
                       + sWin[j * 3 + 0] * sX[b * 3 + 0]
                       + sWin[j * 3 + 1] * sX[b * 3 + 1]
                       + sWin[j * 3 + 2] * sX[b * 3 + 2];
            float acc1 = 0.0f;
            const float4* wr = reinterpret_cast<const float4*>(sW + j * WPAD);
            const float4* hr = reinterpret_cast<const float4*>(sH + b * HDIM);
            #pragma unroll
            for (int k4 = 0; k4 < HDIM / 4; k4++) {
                float4 w = wr[k4];
                float4 h = hr[k4];
                acc0 = fmaf(w.x, h.x, acc0);
                acc1 = fmaf(w.y, h.y, acc1);
                acc0 = fmaf(w.z, h.z, acc0);
                acc1 = fmaf(w.w, h.w, acc1);
            }
            sGate[b * GDIM + j] = acc0 + acc1;
        }
        __syncthreads();

        // cell update + write h1
        for (int idx = tid; idx < BPB * HDIM; idx += NT1) {
            int b = idx / HDIM, k = idx % HDIM;
            const float* gb = sGate + b * GDIM;
            float iv = sigmf(gb[k]);
            float fv = sigmf(gb[HDIM + k]);
            float gv = tanhf(gb[2 * HDIM + k]);
            float ov = sigmf(gb[3 * HDIM + k]);
            float cc = fv * sC[idx] + iv * gv;
            sC[idx] = cc;
            float hh = ov * tanhf(cc);
            sH[idx] = hh;
            // block slab is contiguous: (bg0+b)*HDIM + k = bg0*HDIM + idx
            g_h1[((size_t)t * BATCH + bg0) * HDIM + idx] = hh;
        }
        __syncthreads();
    }
}

// ============================================================================
// Phase 2a: pre1[r][j] = bias[j] + sum_k h1[r][k] * W_ih1[j][k]
// r = t*BATCH + b (1,048,576 rows). Block tile: 128 rows x 80 cols, full k=100.
// Thread tile: 8 rows x 5 cols.
// ============================================================================
#define GA_MT 128
#define GA_NT 80
__global__ void __launch_bounds__(256, 2) gemm_ih1_kernel(
    const float* __restrict__ W,      // [400][100]
    const float* __restrict__ bih,
    const float* __restrict__ bhh)
{
    extern __shared__ float sm[];
    float* sA    = sm;                   // 128*100
    float* sB    = sA + GA_MT * HDIM;    // 80*101 (pad -> conflict-free)
    float* sBias = sB + GA_NT * 101;     // 80

    const int tid = threadIdx.x;
    const size_t rbase = (size_t)blockIdx.y * GA_MT;
    const int cbase = blockIdx.x * GA_NT;

    for (int lin = tid; lin < GA_MT * HDIM; lin += 256)
        sA[lin] = g_h1[rbase * HDIM + lin];
    for (int lin = tid; lin < GA_NT * HDIM; lin += 256)
        sB[(lin / HDIM) * 101 + (lin % HDIM)] = W[(size_t)cbase * HDIM + lin];
    for (int lin = tid; lin < GA_NT; lin += 256)
        sBias[lin] = bih[cbase + lin] + bhh[cbase + lin];
    __syncthreads();

    const int tx = tid & 15;   // col group (5 cols each)
    const int ty = tid >> 4;   // row group (8 rows each)

    float acc[8][5];
    #pragma unroll
    for (int i = 0; i < 8; i++)
        #pragma unroll
        for (int u = 0; u < 5; u++)
            acc[i][u] = sBias[tx * 5 + u];

    #pragma unroll 4
    for (int k = 0; k < HDIM; k++) {
        float a[8], b[5];
        #pragma unroll
        for (int i = 0; i < 8; i++) a[i] = sA[(ty * 8 + i) * HDIM + k];
        #pragma unroll
        for (int u = 0; u < 5; u++) b[u] = sB[(tx * 5 + u) * 101 + k];
        #pragma unroll
        for (int i = 0; i < 8; i++)
            #pragma unroll
            for (int u = 0; u < 5; u++)
                acc[i][u] = fmaf(a[i], b[u], acc[i][u]);
    }

    #pragma unroll
    for (int i = 0; i < 8; i++) {
        size_t row = rbase + ty * 8 + i;
        #pragma unroll
        for (int u = 0; u < 5; u++)
            g_pre1[row * GDIM + cbase + tx * 5 + u] = acc[i][u];
    }
}

// ============================================================================
// Phase 2b: layer-1 recurrence (reads pre1), then the 10x100 FC on last h.
// ============================================================================
__global__ void __launch_bounds__(NT1, 1) lstm_layer1_kernel(
    const float* __restrict__ Whh,    // [400][100]
    const float* __restrict__ fcw,    // [10][100]
    const float* __restrict__ fcb,    // [10]
    float* __restrict__ out)          // [1024][10]
{
    extern __shared__ float sm[];
    float* sW    = sm;                   // 400*104
    float* sGate = sW + GDIM * WPAD;     // 8*400
    float* sH    = sGate + BPB * GDIM;   // 8*100
    float* sC    = sH + BPB * HDIM;      // 8*100

    const int tid = threadIdx.x;
    const int bg0 = blockIdx.x * BPB;

    for (int lin = tid; lin < GDIM * HDIM; lin += NT1)
        sW[(lin / HDIM) * WPAD + (lin % HDIM)] = Whh[lin];
    for (int lin = tid; lin < BPB * HDIM; lin += NT1) { sH[lin] = 0.0f; sC[lin] = 0.0f; }
    __syncthreads();

    for (int t = 0; t < TT; t++) {
        // stage this step's pre-activations (contiguous 8*400 floats)
        const float* pr = g_pre1 + ((size_t)t * BATCH + bg0) * GDIM;
        for (int lin = tid; lin < BPB * GDIM; lin += NT1) sGate[lin] = pr[lin];
        __syncthreads();

        for (int idx = tid; idx < BPB * GDIM; idx += NT1) {
            int b = idx & (BPB - 1);
            int j = idx >> 3;
            float acc0 = sGate[b * GDIM + j];
            float acc1 = 0.0f;
            const float4* wr = reinterpret_cast<const float4*>(sW + j * WPAD);
            const float4* hr = reinterpret_cast<const float4*>(sH + b * HDIM);
            #pragma unroll
            for (int k4 = 0; k4 < HDIM / 4; k4++) {
                float4 w = wr[k4];
                float4 h = hr[k4];
                acc0 = fmaf(w.x, h.x, acc0);
                acc1 = fmaf(w.y, h.y, acc1);
                acc0 = fmaf(w.z, h.z, acc0);
                acc1 = fmaf(w.w, h.w, acc1);
            }
            sGate[b * GDIM + j] = acc0 + acc1;
        }
        __syncthreads();

        for (int idx = tid; idx < BPB * HDIM; idx += NT1) {
            int b = idx / HDIM, k = idx % HDIM;
            const float* gb = sGate + b * GDIM;
            float iv = sigmf(gb[k]);
            float fv = sigmf(gb[HDIM + k]);
            float gv = tanhf(gb[2 * HDIM + k]);
            float ov = sigmf(gb[3 * HDIM + k]);
            float cc = fv * sC[idx] + iv * gv;
            sC[idx] = cc;
            sH[idx] = ov * tanhf(cc);
        }
        __syncthreads();
    }

    // final FC on last hidden state: out[bg0+b][o]
    if (tid < BPB * 10) {
        int b = tid / 10, o = tid % 10;
        float acc = fcb[o];
        const float* wrow = fcw + o * HDIM;
        const float* hrow = sH + b * HDIM;
        #pragma unroll 4
        for (int k = 0; k < HDIM; k++) acc = fmaf(wrow[k], hrow[k], acc);
        out[(bg0 + b) * 10 + o] = acc;
    }
}

// ============================================================================
// launch
// ============================================================================
extern "C" void kernel_launch(void* const* d_in, const int* in_sizes, int n_in,
                              void* d_out, int out_size)
{
    (void)in_sizes; (void)n_in; (void)out_size;
    const float* x     = (const float*)d_in[0];
    const float* Wih0  = (const float*)d_in[1];
    const float* Whh0  = (const float*)d_in[2];
    const float* bih0  = (const float*)d_in[3];
    const float* bhh0  = (const float*)d_in[4];
    const float* Wih1  = (const float*)d_in[5];
    const float* Whh1  = (const float*)d_in[6];
    const float* bih1  = (const float*)d_in[7];
    const float* bhh1  = (const float*)d_in[8];
    const float* fcw   = (const float*)d_in[9];
    const float* fcb   = (const float*)d_in[10];
    float* out = (float*)d_out;

    const size_t smem1  = (size_t)(GDIM * WPAD + GDIM + GDIM * 3 +
                                   BPB * GDIM + 2 * BPB * HDIM + BPB * 3) * 4;
    const size_t smem2a = (size_t)(GA_MT * HDIM + GA_NT * 101 + GA_NT) * 4;
    const size_t smem2b = (size_t)(GDIM * WPAD + BPB * GDIM + 2 * BPB * HDIM) * 4;

    cudaFuncSetAttribute(lstm_layer0_kernel, cudaFuncAttributeMaxDynamicSharedMemorySize, (int)smem1);
    cudaFuncSetAttribute(gemm_ih1_kernel,    cudaFuncAttributeMaxDynamicSharedMemorySize, (int)smem2a);
    cudaFuncSetAttribute(lstm_layer1_kernel, cudaFuncAttributeMaxDynamicSharedMemorySize, (int)smem2b);

    lstm_layer0_kernel<<<NB1, NT1, smem1>>>(x, Wih0, Whh0, bih0, bhh0);

    dim3 g2a(GDIM / GA_NT, (TT * BATCH) / GA_MT);  // (5, 8192)
    gemm_ih1_kernel<<<g2a, 256, smem2a>>>(Wih1, bih1, bhh1);

    lstm_layer1_kernel<<<NB1, NT1, smem2b>>>(Whh1, fcw, fcb, out);
}

// round 4
// speedup vs baseline: 1.9306x; 1.9306x over previous
#include <cuda_runtime.h>
#include <math.h>

#define TT    1024
#define BATCH 1024
#define HDIM  100
#define GDIM  400
#define WPAD  104            // padded W row: 104 = 8*13 -> every row 32B-aligned
#define BPB   8
#define NB1   (BATCH / BPB)  // 128 persistent blocks
#define NT1   800            // thread <-> (b in 0..7, j0 in 0..99)

typedef unsigned long long u64;

__device__ float g_h1[(size_t)TT * BATCH * HDIM];    // layer-0 hidden states
__device__ float g_pre1[(size_t)TT * BATCH * GDIM];  // layer-1 gate pre-activations

__device__ __forceinline__ float sigmf(float x) { return 1.0f / (1.0f + __expf(-x)); }

__device__ __forceinline__ u64 ffma2(u64 a, u64 b, u64 c) {
    u64 d;
    asm("fma.rn.f32x2 %0, %1, %2, %3;" : "=l"(d) : "l"(a), "l"(b), "l"(c));
    return d;
}
__device__ __forceinline__ float hsum2(u64 v) {
    float lo, hi;
    asm("mov.b64 {%0, %1}, %2;" : "=f"(lo), "=f"(hi) : "l"(v));
    return lo + hi;
}

// ============================================================================
// Layer-0 recurrence. Thread owns (b, j0): all 4 gates + in-register cell state.
// One barrier per step (double-buffered h).
// ============================================================================
__global__ void __launch_bounds__(NT1, 1) lstm_layer0_kernel(
    const float* __restrict__ x,      // [1024][3][1024]
    const float* __restrict__ Wih,    // [400][3]
    const float* __restrict__ Whh,    // [400][100]
    const float* __restrict__ bih,
    const float* __restrict__ bhh)
{
    extern __shared__ float sm[];
    float* sW    = sm;                   // 400*104
    float* sWin  = sW + GDIM * WPAD;     // 400*4
    float* sBias = sWin + GDIM * 4;      // 400
    float* sH0   = sBias + GDIM;         // 800
    float* sH1   = sH0 + NT1;            // 800

    const int tid = threadIdx.x;
    const int b   = tid & 7;
    const int j0  = tid >> 3;            // 0..99
    const int bg0 = blockIdx.x * BPB;

    for (int lin = tid; lin < GDIM * HDIM; lin += NT1)
        sW[(lin / HDIM) * WPAD + (lin % HDIM)] = Whh[lin];
    for (int lin = tid; lin < GDIM * 3; lin += NT1)
        sWin[(lin / 3) * 4 + (lin % 3)] = Wih[lin];
    for (int lin = tid; lin < GDIM; lin += NT1) sBias[lin] = bih[lin] + bhh[lin];
    sH0[tid] = 0.0f;
    __syncthreads();

    // loop-invariant per-thread constants
    float bi[4], wi[4][3];
    #pragma unroll
    for (int g = 0; g < 4; g++) {
        bi[g] = sBias[g * HDIM + j0];
        wi[g][0] = sWin[(g * HDIM + j0) * 4 + 0];
        wi[g][1] = sWin[(g * HDIM + j0) * 4 + 1];
        wi[g][2] = sWin[(g * HDIM + j0) * 4 + 2];
    }
    const ulonglong2* wp0 = (const ulonglong2*)(sW + (0 * HDIM + j0) * WPAD);
    const ulonglong2* wp1 = (const ulonglong2*)(sW + (1 * HDIM + j0) * WPAD);
    const ulonglong2* wp2 = (const ulonglong2*)(sW + (2 * HDIM + j0) * WPAD);
    const ulonglong2* wp3 = (const ulonglong2*)(sW + (3 * HDIM + j0) * WPAD);
    const float* xb = x + (size_t)(bg0 + b) * 3072;

    float cReg = 0.0f;
    float* sHr = sH0;
    float* sHw = sH1;

    for (int t = 0; t < TT; t++) {
        float x0 = xb[t], x1 = xb[1024 + t], x2 = xb[2048 + t];
        u64 a0 = 0, a1 = 0, a2 = 0, a3 = 0;
        const ulonglong2* hp = (const ulonglong2*)(sHr + b * HDIM);
        #pragma unroll
        for (int k4 = 0; k4 < HDIM / 4; k4++) {
            ulonglong2 h2 = hp[k4];
            ulonglong2 w;
            w = wp0[k4]; a0 = ffma2(w.x, h2.x, a0); a0 = ffma2(w.y, h2.y, a0);
            w = wp1[k4]; a1 = ffma2(w.x, h2.x, a1); a1 = ffma2(w.y, h2.y, a1);
            w = wp2[k4]; a2 = ffma2(w.x, h2.x, a2); a2 = ffma2(w.y, h2.y, a2);
            w = wp3[k4]; a3 = ffma2(w.x, h2.x, a3); a3 = ffma2(w.y, h2.y, a3);
        }
        float gi = hsum2(a0) + bi[0] + wi[0][0]*x0 + wi[0][1]*x1 + wi[0][2]*x2;
        float gf = hsum2(a1) + bi[1] + wi[1][0]*x0 + wi[1][1]*x1 + wi[1][2]*x2;
        float gg = hsum2(a2) + bi[2] + wi[2][0]*x0 + wi[2][1]*x1 + wi[2][2]*x2;
        float go = hsum2(a3) + bi[3] + wi[3][0]*x0 + wi[3][1]*x1 + wi[3][2]*x2;

        float iv = sigmf(gi), fv = sigmf(gf), gv = tanhf(gg), ov = sigmf(go);
        cReg = fv * cReg + iv * gv;
        float hv = ov * tanhf(cReg);
        sHw[b * HDIM + j0] = hv;
        g_h1[((size_t)t * BATCH + bg0 + b) * HDIM + j0] = hv;

        float* tmp = sHr; sHr = sHw; sHw = tmp;
        __syncthreads();
    }
}

// ============================================================================
// Layer-1 input GEMM: pre1[r][j] = bias[j] + sum_k h1[r][k]*W_ih1[j][k]
// Block 128x80, thread 8x5, f32x2 over k-pairs.
// ============================================================================
#define GA_MT 128
#define GA_NT 80
__global__ void __launch_bounds__(256, 2) gemm_ih1_kernel(
    const float* __restrict__ W,      // [400][100]
    const float* __restrict__ bih,
    const float* __restrict__ bhh)
{
    extern __shared__ float sm[];
    float* sA = sm;                   // 128*100
    float* sB = sA + GA_MT * HDIM;    // 80*102 (pad: 8B-aligned k-pairs)

    const int tid = threadIdx.x;
    const size_t rbase = (size_t)blockIdx.y * GA_MT;
    const int cbase = blockIdx.x * GA_NT;

    for (int lin = tid; lin < GA_MT * HDIM; lin += 256)
        sA[lin] = g_h1[rbase * HDIM + lin];
    for (int lin = tid; lin < GA_NT * HDIM; lin += 256)
        sB[(lin / HDIM) * 102 + (lin % HDIM)] = W[(size_t)cbase * HDIM + lin];
    __syncthreads();

    const int tx = tid & 15;   // 5 cols each
    const int ty = tid >> 4;   // 8 rows each

    u64 acc[8][5];
    #pragma unroll
    for (int i = 0; i < 8; i++)
        #pragma unroll
        for (int u = 0; u < 5; u++) acc[i][u] = 0ULL;

    #pragma unroll 5
    for (int kp = 0; kp < HDIM / 2; kp++) {
        u64 b2[5];
        #pragma unroll
        for (int u = 0; u < 5; u++)
            b2[u] = *(const u64*)(sB + (tx * 5 + u) * 102 + 2 * kp);
        #pragma unroll
        for (int i = 0; i < 8; i++) {
            u64 a2 = *(const u64*)(sA + (ty * 8 + i) * HDIM + 2 * kp);
            #pragma unroll
            for (int u = 0; u < 5; u++)
                acc[i][u] = ffma2(a2, b2[u], acc[i][u]);
        }
    }

    float bias[5];
    #pragma unroll
    for (int u = 0; u < 5; u++) {
        int col = cbase + tx * 5 + u;
        bias[u] = bih[col] + bhh[col];
    }
    #pragma unroll
    for (int i = 0; i < 8; i++) {
        size_t row = rbase + ty * 8 + i;
        #pragma unroll
        for (int u = 0; u < 5; u++)
            g_pre1[row * GDIM + cbase + tx * 5 + u] = hsum2(acc[i][u]) + bias[u];
    }
}

// ============================================================================
// Layer-1 recurrence (pre1 precomputed) + fused 10x100 FC.
// ============================================================================
__global__ void __launch_bounds__(NT1, 1) lstm_layer1_kernel(
    const float* __restrict__ Whh,    // [400][100]
    const float* __restrict__ fcw,    // [10][100]
    const float* __restrict__ fcb,    // [10]
    float* __restrict__ out)          // [1024][10]
{
    extern __shared__ float sm[];
    float* sW  = sm;                  // 400*104
    float* sH0 = sW + GDIM * WPAD;    // 800
    float* sH1 = sH0 + NT1;           // 800

    const int tid = threadIdx.x;
    const int b   = tid & 7;
    const int j0  = tid >> 3;
    const int bg0 = blockIdx.x * BPB;

    for (int lin = tid; lin < GDIM * HDIM; lin += NT1)
        sW[(lin / HDIM) * WPAD + (lin % HDIM)] = Whh[lin];
    sH0[tid] = 0.0f;
    __syncthreads();

    const ulonglong2* wp0 = (const ulonglong2*)(sW + (0 * HDIM + j0) * WPAD);
    const ulonglong2* wp1 = (const ulonglong2*)(sW + (1 * HDIM + j0) * WPAD);
    const ulonglong2* wp2 = (const ulonglong2*)(sW + (2 * HDIM + j0) * WPAD);
    const ulonglong2* wp3 = (const ulonglong2*)(sW + (3 * HDIM + j0) * WPAD);

    float cReg = 0.0f;
    float* sHr = sH0;
    float* sHw = sH1;

    for (int t = 0; t < TT; t++) {
        const float* pr = g_pre1 + ((size_t)t * BATCH + bg0 + b) * GDIM;
        float p0 = pr[j0], p1 = pr[HDIM + j0], p2 = pr[2 * HDIM + j0], p3 = pr[3 * HDIM + j0];

        u64 a0 = 0, a1 = 0, a2 = 0, a3 = 0;
        const ulonglong2* hp = (const ulonglong2*)(sHr + b * HDIM);
        #pragma unroll
        for (int k4 = 0; k4 < HDIM / 4; k4++) {
            ulonglong2 h2 = hp[k4];
            ulonglong2 w;
            w = wp0[k4]; a0 = ffma2(w.x, h2.x, a0); a0 = ffma2(w.y, h2.y, a0);
            w = wp1[k4]; a1 = ffma2(w.x, h2.x, a1); a1 = ffma2(w.y, h2.y, a1);
            w = wp2[k4]; a2 = ffma2(w.x, h2.x, a2); a2 = ffma2(w.y, h2.y, a2);
            w = wp3[k4]; a3 = ffma2(w.x, h2.x, a3); a3 = ffma2(w.y, h2.y, a3);
        }
        float gi = hsum2(a0) + p0;
        float gf = hsum2(a1) + p1;
        float gg = hsum2(a2) + p2;
        float go = hsum2(a3) + p3;

        float iv = sigmf(gi), fv = sigmf(gf), gv = tanhf(gg), ov = sigmf(go);
        cReg = fv * cReg + iv * gv;
        sHw[b * HDIM + j0] = ov * tanhf(cReg);

        float* tmp = sHr; sHr = sHw; sHw = tmp;
        __syncthreads();
    }

    if (tid < BPB * 10) {
        int bb = tid / 10, o = tid % 10;
        float acc = fcb[o];
        const float* wrow = fcw + o * HDIM;
        const float* hrow = sHr + bb * HDIM;
        #pragma unroll 4
        for (int k = 0; k < HDIM; k++) acc = fmaf(wrow[k], hrow[k], acc);
        out[(bg0 + bb) * 10 + o] = acc;
    }
}

// ============================================================================
extern "C" void kernel_launch(void* const* d_in, const int* in_sizes, int n_in,
                              void* d_out, int out_size)
{
    (void)in_sizes; (void)n_in; (void)out_size;
    const float* x    = (const float*)d_in[0];
    const float* Wih0 = (const float*)d_in[1];
    const float* Whh0 = (const float*)d_in[2];
    const float* bih0 = (const float*)d_in[3];
    const float* bhh0 = (const float*)d_in[4];
    const float* Wih1 = (const float*)d_in[5];
    const float* Whh1 = (const float*)d_in[6];
    const float* bih1 = (const float*)d_in[7];
    const float* bhh1 = (const float*)d_in[8];
    const float* fcw  = (const float*)d_in[9];
    const float* fcb  = (const float*)d_in[10];
    float* out = (float*)d_out;

    const size_t smem0 = (size_t)(GDIM * WPAD + GDIM * 4 + GDIM + 2 * NT1) * 4;
    const size_t smemA = (size_t)(GA_MT * HDIM + GA_NT * 102) * 4;
    const size_t smem1 = (size_t)(GDIM * WPAD + 2 * NT1) * 4;

    cudaFuncSetAttribute(lstm_layer0_kernel, cudaFuncAttributeMaxDynamicSharedMemorySize, (int)smem0);
    cudaFuncSetAttribute(gemm_ih1_kernel,    cudaFuncAttributeMaxDynamicSharedMemorySize, (int)smemA);
    cudaFuncSetAttribute(lstm_layer1_kernel, cudaFuncAttributeMaxDynamicSharedMemorySize, (int)smem1);

    lstm_layer0_kernel<<<NB1, NT1, smem0>>>(x, Wih0, Whh0, bih0, bhh0);

    dim3 g2a(GDIM / GA_NT, (TT * BATCH) / GA_MT);  // (5, 8192)
    gemm_ih1_kernel<<<g2a, 256, smemA>>>(Wih1, bih1, bhh1);

    lstm_layer1_kernel<<<NB1, NT1, smem1>>>(Whh1, fcw, fcb, out);
}

// round 5
// speedup vs baseline: 2.2492x; 1.1651x over previous
#include <cuda_runtime.h>
#include <math.h>

#define TT    1024
#define BATCH 1024
#define HDIM  100
#define GDIM  400
#define BPB   8              // batch elems per block
#define NB1   (BATCH / BPB)  // 128 persistent blocks
#define NT1   400            // thread <-> (batch-pair bp in 0..3, j0 in 0..99)

typedef unsigned long long u64;

__device__ float g_h1[(size_t)TT * BATCH * HDIM];    // layer-0 hidden states
__device__ float g_pre1[(size_t)TT * BATCH * GDIM];  // layer-1 gate pre-activations

__device__ __forceinline__ float sigmf(float x) { return 1.0f / (1.0f + __expf(-x)); }
__device__ __forceinline__ float tanh_fast(float x) {
    // 1 - 2/(e^{2x}+1): MUFU-based, ~1e-7 rel err, saturates correctly at +/-inf
    float t = __expf(2.0f * x);
    return 1.0f - __fdividef(2.0f, t + 1.0f);
}

__device__ __forceinline__ u64 ffma2(u64 a, u64 b, u64 c) {
    u64 d;
    asm("fma.rn.f32x2 %0, %1, %2, %3;" : "=l"(d) : "l"(a), "l"(b), "l"(c));
    return d;
}
__device__ __forceinline__ float hsum2(u64 v) {
    float lo, hi;
    asm("mov.b64 {%0, %1}, %2;" : "=f"(lo), "=f"(hi) : "l"(v));
    return lo + hi;
}

// ============================================================================
// Layer-0 recurrence. Thread owns (batch-pair, j0): 8 gates, 2 in-register cells.
// W rows loaded once per iter, reused for both batch elems. One barrier/step.
// ============================================================================
__global__ void __launch_bounds__(NT1, 1) lstm_layer0_kernel(
    const float* __restrict__ x,      // [1024][3][1024]
    const float* __restrict__ Wih,    // [400][3]
    const float* __restrict__ Whh,    // [400][100]
    const float* __restrict__ bih,
    const float* __restrict__ bhh)
{
    extern __shared__ float sm[];
    float* sW    = sm;                   // 400*100 (row stride 100 -> conflict-free)
    float* sWin  = sW + GDIM * HDIM;     // 400*4
    float* sBias = sWin + GDIM * 4;      // 400
    float* sH0   = sBias + GDIM;         // 800
    float* sH1   = sH0 + BPB * HDIM;     // 800

    const int tid = threadIdx.x;
    const int bp  = tid & 3;
    const int j0  = tid >> 2;            // 0..99
    const int b0  = 2 * bp, b1 = b0 + 1;
    const int bg0 = blockIdx.x * BPB;

    for (int lin = tid; lin < GDIM * HDIM; lin += NT1) sW[lin] = Whh[lin];
    for (int lin = tid; lin < GDIM * 3; lin += NT1)
        sWin[(lin / 3) * 4 + (lin % 3)] = Wih[lin];
    for (int lin = tid; lin < GDIM; lin += NT1) sBias[lin] = bih[lin] + bhh[lin];
    for (int lin = tid; lin < BPB * HDIM; lin += NT1) sH0[lin] = 0.0f;
    __syncthreads();

    float bi[4], wi[4][3];
    #pragma unroll
    for (int g = 0; g < 4; g++) {
        bi[g] = sBias[g * HDIM + j0];
        wi[g][0] = sWin[(g * HDIM + j0) * 4 + 0];
        wi[g][1] = sWin[(g * HDIM + j0) * 4 + 1];
        wi[g][2] = sWin[(g * HDIM + j0) * 4 + 2];
    }
    const ulonglong2* wp0 = (const ulonglong2*)(sW + (0 * HDIM + j0) * HDIM);
    const ulonglong2* wp1 = (const ulonglong2*)(sW + (1 * HDIM + j0) * HDIM);
    const ulonglong2* wp2 = (const ulonglong2*)(sW + (2 * HDIM + j0) * HDIM);
    const ulonglong2* wp3 = (const ulonglong2*)(sW + (3 * HDIM + j0) * HDIM);
    const float* xa = x + (size_t)(bg0 + b0) * 3072;
    const float* xb = x + (size_t)(bg0 + b1) * 3072;

    float c0 = 0.0f, c1 = 0.0f;
    float* sHr = sH0;
    float* sHw = sH1;

    for (int t = 0; t < TT; t++) {
        float xa0 = xa[t], xa1 = xa[1024 + t], xa2 = xa[2048 + t];
        float xb0 = xb[t], xb1 = xb[1024 + t], xb2 = xb[2048 + t];

        u64 a00 = 0, a01 = 0, a02 = 0, a03 = 0;   // batch b0, gates i f g o
        u64 a10 = 0, a11 = 0, a12 = 0, a13 = 0;   // batch b1
        const ulonglong2* hpa = (const ulonglong2*)(sHr + b0 * HDIM);
        const ulonglong2* hpb = (const ulonglong2*)(sHr + b1 * HDIM);
        #pragma unroll
        for (int k4 = 0; k4 < HDIM / 4; k4++) {
            ulonglong2 ha = hpa[k4];
            ulonglong2 hb = hpb[k4];
            ulonglong2 w;
            w = wp0[k4];
            a00 = ffma2(w.x, ha.x, a00); a00 = ffma2(w.y, ha.y, a00);
            a10 = ffma2(w.x, hb.x, a10); a10 = ffma2(w.y, hb.y, a10);
            w = wp1[k4];
            a01 = ffma2(w.x, ha.x, a01); a01 = ffma2(w.y, ha.y, a01);
            a11 = ffma2(w.x, hb.x, a11); a11 = ffma2(w.y, hb.y, a11);
            w = wp2[k4];
            a02 = ffma2(w.x, ha.x, a02); a02 = ffma2(w.y, ha.y, a02);
            a12 = ffma2(w.x, hb.x, a12); a12 = ffma2(w.y, hb.y, a12);
            w = wp3[k4];
            a03 = ffma2(w.x, ha.x, a03); a03 = ffma2(w.y, ha.y, a03);
            a13 = ffma2(w.x, hb.x, a13); a13 = ffma2(w.y, hb.y, a13);
        }

        float gi0 = hsum2(a00) + bi[0] + wi[0][0]*xa0 + wi[0][1]*xa1 + wi[0][2]*xa2;
        float gf0 = hsum2(a01) + bi[1] + wi[1][0]*xa0 + wi[1][1]*xa1 + wi[1][2]*xa2;
        float gg0 = hsum2(a02) + bi[2] + wi[2][0]*xa0 + wi[2][1]*xa1 + wi[2][2]*xa2;
        float go0 = hsum2(a03) + bi[3] + wi[3][0]*xa0 + wi[3][1]*xa1 + wi[3][2]*xa2;
        float gi1 = hsum2(a10) + bi[0] + wi[0][0]*xb0 + wi[0][1]*xb1 + wi[0][2]*xb2;
        float gf1 = hsum2(a11) + bi[1] + wi[1][0]*xb0 + wi[1][1]*xb1 + wi[1][2]*xb2;
        float gg1 = hsum2(a12) + bi[2] + wi[2][0]*xb0 + wi[2][1]*xb1 + wi[2][2]*xb2;
        float go1 = hsum2(a13) + bi[3] + wi[3][0]*xb0 + wi[3][1]*xb1 + wi[3][2]*xb2;

        c0 = sigmf(gf0) * c0 + sigmf(gi0) * tanh_fast(gg0);
        c1 = sigmf(gf1) * c1 + sigmf(gi1) * tanh_fast(gg1);
        float h0 = sigmf(go0) * tanh_fast(c0);
        float h1v = sigmf(go1) * tanh_fast(c1);

        sHw[b0 * HDIM + j0] = h0;
        sHw[b1 * HDIM + j0] = h1v;
        size_t rowbase = ((size_t)t * BATCH + bg0);
        g_h1[(rowbase + b0) * HDIM + j0] = h0;
        g_h1[(rowbase + b1) * HDIM + j0] = h1v;

        float* tmp = sHr; sHr = sHw; sHw = tmp;
        __syncthreads();
    }
}

// ============================================================================
// Layer-1 input GEMM: pre1[r][j] = bias[j] + sum_k h1[r][k]*W_ih1[j][k]
// ============================================================================
#define GA_MT 128
#define GA_NT 80
__global__ void __launch_bounds__(256, 2) gemm_ih1_kernel(
    const float* __restrict__ W,      // [400][100]
    const float* __restrict__ bih,
    const float* __restrict__ bhh)
{
    extern __shared__ float sm[];
    float* sA = sm;                   // 128*100
    float* sB = sA + GA_MT * HDIM;    // 80*102

    const int tid = threadIdx.x;
    const size_t rbase = (size_t)blockIdx.y * GA_MT;
    const int cbase = blockIdx.x * GA_NT;

    for (int lin = tid; lin < GA_MT * HDIM; lin += 256)
        sA[lin] = g_h1[rbase * HDIM + lin];
    for (int lin = tid; lin < GA_NT * HDIM; lin += 256)
        sB[(lin / HDIM) * 102 + (lin % HDIM)] = W[(size_t)cbase * HDIM + lin];
    __syncthreads();

    const int tx = tid & 15;
    const int ty = tid >> 4;

    u64 acc[8][5];
    #pragma unroll
    for (int i = 0; i < 8; i++)
        #pragma unroll
        for (int u = 0; u < 5; u++) acc[i][u] = 0ULL;

    #pragma unroll 5
    for (int kp = 0; kp < HDIM / 2; kp++) {
        u64 b2[5];
        #pragma unroll
        for (int u = 0; u < 5; u++)
            b2[u] = *(const u64*)(sB + (tx * 5 + u) * 102 + 2 * kp);
        #pragma unroll
        for (int i = 0; i < 8; i++) {
            u64 a2 = *(const u64*)(sA + (ty * 8 + i) * HDIM + 2 * kp);
            #pragma unroll
            for (int u = 0; u < 5; u++)
                acc[i][u] = ffma2(a2, b2[u], acc[i][u]);
        }
    }

    float bias[5];
    #pragma unroll
    for (int u = 0; u < 5; u++) {
        int col = cbase + tx * 5 + u;
        bias[u] = bih[col] + bhh[col];
    }
    #pragma unroll
    for (int i = 0; i < 8; i++) {
        size_t row = rbase + ty * 8 + i;
        #pragma unroll
        for (int u = 0; u < 5; u++)
            g_pre1[row * GDIM + cbase + tx * 5 + u] = hsum2(acc[i][u]) + bias[u];
    }
}

// ============================================================================
// Layer-1 recurrence (pre1 precomputed) + fused 10x100 FC.
// ============================================================================
__global__ void __launch_bounds__(NT1, 1) lstm_layer1_kernel(
    const float* __restrict__ Whh,    // [400][100]
    const float* __restrict__ fcw,    // [10][100]
    const float* __restrict__ fcb,    // [10]
    float* __restrict__ out)          // [1024][10]
{
    extern __shared__ float sm[];
    float* sW  = sm;                  // 400*100
    float* sH0 = sW + GDIM * HDIM;    // 800
    float* sH1 = sH0 + BPB * HDIM;    // 800

    const int tid = threadIdx.x;
    const int bp  = tid & 3;
    const int j0  = tid >> 2;
    const int b0  = 2 * bp, b1 = b0 + 1;
    const int bg0 = blockIdx.x * BPB;

    for (int lin = tid; lin < GDIM * HDIM; lin += NT1) sW[lin] = Whh[lin];
    for (int lin = tid; lin < BPB * HDIM; lin += NT1) sH0[lin] = 0.0f;
    __syncthreads();

    const ulonglong2* wp0 = (const ulonglong2*)(sW + (0 * HDIM + j0) * HDIM);
    const ulonglong2* wp1 = (const ulonglong2*)(sW + (1 * HDIM + j0) * HDIM);
    const ulonglong2* wp2 = (const ulonglong2*)(sW + (2 * HDIM + j0) * HDIM);
    const ulonglong2* wp3 = (const ulonglong2*)(sW + (3 * HDIM + j0) * HDIM);

    float c0 = 0.0f, c1 = 0.0f;
    float* sHr = sH0;
    float* sHw = sH1;

    for (int t = 0; t < TT; t++) {
        // prefetch this step's pre-activations (gmem, hidden under the matvec)
        const float* pra = g_pre1 + ((size_t)t * BATCH + bg0 + b0) * GDIM + j0;
        const float* prb = g_pre1 + ((size_t)t * BATCH + bg0 + b1) * GDIM + j0;
        float p00 = pra[0], p01 = pra[HDIM], p02 = pra[2 * HDIM], p03 = pra[3 * HDIM];
        float p10 = prb[0], p11 = prb[HDIM], p12 = prb[2 * HDIM], p13 = prb[3 * HDIM];

        u64 a00 = 0, a01 = 0, a02 = 0, a03 = 0;
        u64 a10 = 0, a11 = 0, a12 = 0, a13 = 0;
        const ulonglong2* hpa = (const ulonglong2*)(sHr + b0 * HDIM);
        const ulonglong2* hpb = (const ulonglong2*)(sHr + b1 * HDIM);
        #pragma unroll
        for (int k4 = 0; k4 < HDIM / 4; k4++) {
            ulonglong2 ha = hpa[k4];
            ulonglong2 hb = hpb[k4];
            ulonglong2 w;
            w = wp0[k4];
            a00 = ffma2(w.x, ha.x, a00); a00 = ffma2(w.y, ha.y, a00);
            a10 = ffma2(w.x, hb.x, a10); a10 = ffma2(w.y, hb.y, a10);
            w = wp1[k4];
            a01 = ffma2(w.x, ha.x, a01); a01 = ffma2(w.y, ha.y, a01);
            a11 = ffma2(w.x, hb.x, a11); a11 = ffma2(w.y, hb.y, a11);
            w = wp2[k4];
            a02 = ffma2(w.x, ha.x, a02); a02 = ffma2(w.y, ha.y, a02);
            a12 = ffma2(w.x, hb.x, a12); a12 = ffma2(w.y, hb.y, a12);
            w = wp3[k4];
            a03 = ffma2(w.x, ha.x, a03); a03 = ffma2(w.y, ha.y, a03);
            a13 = ffma2(w.x, hb.x, a13); a13 = ffma2(w.y, hb.y, a13);
        }

        float gi0 = hsum2(a00) + p00, gf0 = hsum2(a01) + p01;
        float gg0 = hsum2(a02) + p02, go0 = hsum2(a03) + p03;
        float gi1 = hsum2(a10) + p10, gf1 = hsum2(a11) + p11;
        float gg1 = hsum2(a12) + p12, go1 = hsum2(a13) + p13;

        c0 = sigmf(gf0) * c0 + sigmf(gi0) * tanh_fast(gg0);
        c1 = sigmf(gf1) * c1 + sigmf(gi1) * tanh_fast(gg1);
        sHw[b0 * HDIM + j0] = sigmf(go0) * tanh_fast(c0);
        sHw[b1 * HDIM + j0] = sigmf(go1) * tanh_fast(c1);

        float* tmp = sHr; sHr = sHw; sHw = tmp;
        __syncthreads();
    }

    if (tid < BPB * 10) {
        int bb = tid / 10, o = tid % 10;
        float acc = fcb[o];
        const float* wrow = fcw + o * HDIM;
        const float* hrow = sHr + bb * HDIM;
        #pragma unroll 4
        for (int k = 0; k < HDIM; k++) acc = fmaf(wrow[k], hrow[k], acc);
        out[(bg0 + bb) * 10 + o] = acc;
    }
}

// ============================================================================
extern "C" void kernel_launch(void* const* d_in, const int* in_sizes, int n_in,
                              void* d_out, int out_size)
{
    (void)in_sizes; (void)n_in; (void)out_size;
    const float* x    = (const float*)d_in[0];
    const float* Wih0 = (const float*)d_in[1];
    const float* Whh0 = (const float*)d_in[2];
    const float* bih0 = (const float*)d_in[3];
    const float* bhh0 = (const float*)d_in[4];
    const float* Wih1 = (const float*)d_in[5];
    const float* Whh1 = (const float*)d_in[6];
    const float* bih1 = (const float*)d_in[7];
    const float* bhh1 = (const float*)d_in[8];
    const float* fcw  = (const float*)d_in[9];
    const float* fcb  = (const float*)d_in[10];
    float* out = (float*)d_out;

    const size_t smem0 = (size_t)(GDIM * HDIM + GDIM * 4 + GDIM + 2 * BPB * HDIM) * 4;
    const size_t smemA = (size_t)(GA_MT * HDIM + GA_NT * 102) * 4;
    const size_t smem1 = (size_t)(GDIM * HDIM + 2 * BPB * HDIM) * 4;

    cudaFuncSetAttribute(lstm_layer0_kernel, cudaFuncAttributeMaxDynamicSharedMemorySize, (int)smem0);
    cudaFuncSetAttribute(gemm_ih1_kernel,    cudaFuncAttributeMaxDynamicSharedMemorySize, (int)smemA);
    cudaFuncSetAttribute(lstm_layer1_kernel, cudaFuncAttributeMaxDynamicSharedMemorySize, (int)smem1);

    lstm_layer0_kernel<<<NB1, NT1, smem0>>>(x, Wih0, Whh0, bih0, bhh0);

    dim3 g2a(GDIM / GA_NT, (TT * BATCH) / GA_MT);  // (5, 8192)
    gemm_ih1_kernel<<<g2a, 256, smemA>>>(Wih1, bih1, bhh1);

    lstm_layer1_kernel<<<NB1, NT1, smem1>>>(Whh1, fcw, fcb, out);
}